// round 4
// baseline (speedup 1.0000x reference)
#include <cuda_runtime.h>
#include <cstdint>

// SNN: fc1(21->100) -> 25-step Leaky -> fc2(100->10) -> Leaky
// Numerics (match XLA fp32 reference):
//  - cur1: acc=0, FMA k ascending, + b1 at end (single chain)
//  - spk is exactly {0,1} in fp32 (proved: fl(fl(1-s)+s)=1 for s in (0,0.5)),
//    so cur2 == ordered sum of W2 columns over active j ascending, + b2 at end.
//  - membrane update CONTRACTED: mem = fl(fma(beta, mem, cur) - reset)
//    (XLA fuses mul+add into fma; subtract stays separate).
// Layout: 4 threads/sample (25 hidden neurons each); spike masks shared via
// shfl; 10 outputs as 5 f32x2 pairs (tsub0: pairs 0,4; tsub1..3: pairs 1..3),
// each pair an unbroken sequential add chain.

#define BETA    0.99f
#define NSTEPS  25
#define H1      100
#define H2      10
#define NIN     21
#define JPT     25
#define SPB     64

typedef unsigned long long u64;
typedef unsigned int u32;

__device__ __forceinline__ u64 add2(u64 a, u64 b) {
    u64 d;
    asm("add.rn.f32x2 %0, %1, %2;" : "=l"(d) : "l"(a), "l"(b));
    return d;
}
__device__ __forceinline__ void unpack2(u64 v, float& a, float& b) {
    asm("mov.b64 {%0, %1}, %2;" : "=f"(a), "=f"(b) : "l"(v));
}

__global__ __launch_bounds__(256)
void snn_kernel(const float* __restrict__ x,
                const float* __restrict__ W1,
                const float* __restrict__ b1,
                const float* __restrict__ W2,
                const float* __restrict__ b2,
                float* __restrict__ out,
                int B)
{
    __shared__ __align__(16) float W1s[H1][24];   // [j][k], row padded
    __shared__ __align__(16) float W2s[H1][12];   // [j][k] transposed, padded
    __shared__ __align__(16) float b1s[H1];
    __shared__ __align__(16) float b2s[12];

    const int tid = threadIdx.x;

    for (int idx = tid; idx < H1 * NIN; idx += 256)
        W1s[idx / NIN][idx % NIN] = W1[idx];
    for (int idx = tid; idx < H2 * H1; idx += 256)
        W2s[idx % H1][idx / H1] = W2[idx];          // W2 is [10][100]
    if (tid < H1) b1s[tid] = b1[tid];
    if (tid < 12) b2s[tid] = (tid < H2) ? b2[tid] : 0.0f;
    __syncthreads();

    const int tsub   = tid & 3;
    const int sample = blockIdx.x * SPB + (tid >> 2);
    if (sample >= B) return;
    const int jbase = tsub * JPT;

    // ---- x row ----
    float xr[NIN];
    const float* xrow = x + (size_t)sample * NIN;
#pragma unroll
    for (int i = 0; i < NIN; i++) xr[i] = __ldg(xrow + i);

    // ---- cur1: acc=0, FMA k ascending, then + b1 ----
    float cur1[JPT];
#pragma unroll
    for (int jj = 0; jj < JPT; jj++) {
        const float* w = &W1s[jbase + jj][0];
        float acc = 0.0f;
#pragma unroll
        for (int k = 0; k < NIN; k++)
            acc = __fmaf_rn(xr[k], w[k], acc);
        cur1[jj] = __fadd_rn(acc, b1s[jbase + jj]);
    }

    // ---- state ----
    float mem1[JPT];
#pragma unroll
    for (int jj = 0; jj < JPT; jj++) mem1[jj] = 0.0f;
    u32 spkmask = 0;

    const int pairA = tsub;
    const bool hasB = (tsub == 0);
    const int offA = 2 * pairA;
    const int offB = 8;
    float mem2A0 = 0.f, mem2A1 = 0.f, spk2A0 = 0.f, spk2A1 = 0.f;
    float mem2B0 = 0.f, mem2B1 = 0.f, spk2B0 = 0.f, spk2B1 = 0.f;
    const u64 b2A = *(const u64*)&b2s[offA];
    const u64 b2B = *(const u64*)&b2s[offB];

    float* spkout = out + (size_t)sample * H2;
    float* memout = spkout + (size_t)NSTEPS * B * H2;
    const size_t step_stride = (size_t)B * H2;
    const int lanebase = (tid & 31) & ~3;

#pragma unroll 1
    for (int t = 0; t < NSTEPS; t++) {
        // ---- layer-1: mem = fl(fma(beta, mem, cur) - reset) ----
        u32 newmask = 0;
#pragma unroll
        for (int jj = 0; jj < JPT; jj++) {
            float r = (float)((spkmask >> jj) & 1u);
            float m = __fmaf_rn(BETA, mem1[jj], cur1[jj]);
            m = __fsub_rn(m, r);
            mem1[jj] = m;
            newmask |= (m > 1.0f) ? (1u << jj) : 0u;
        }
        spkmask = newmask;

        // ---- cur2: ordered sum of W2 columns over active j (ascending) ----
        u64 accA = 0ull, accB = 0ull;
#pragma unroll
        for (int sp = 0; sp < 4; sp++) {
            u32 m = __shfl_sync(0xffffffffu, spkmask, lanebase + sp, 32);
            const float* wbase = &W2s[sp * JPT][0];
            while (m) {
                int b = __ffs(m) - 1;
                m &= m - 1;
                const float* w = wbase + b * 12;
                accA = add2(accA, *(const u64*)(w + offA));
                if (hasB) accB = add2(accB, *(const u64*)(w + offB));
            }
        }
        accA = add2(accA, b2A);
        float c2A0, c2A1; unpack2(accA, c2A0, c2A1);

        // ---- layer-2: mem = fl(fma(beta, mem, cur) - reset) ----
        {
            float m0 = __fsub_rn(__fmaf_rn(BETA, mem2A0, c2A0), spk2A0);
            float m1 = __fsub_rn(__fmaf_rn(BETA, mem2A1, c2A1), spk2A1);
            mem2A0 = m0; mem2A1 = m1;
            spk2A0 = (m0 > 1.0f) ? 1.0f : 0.0f;
            spk2A1 = (m1 > 1.0f) ? 1.0f : 0.0f;
            float2 sv; sv.x = spk2A0; sv.y = spk2A1;
            *(float2*)(spkout + offA) = sv;
            float2 mv; mv.x = m0; mv.y = m1;
            *(float2*)(memout + offA) = mv;
        }
        if (hasB) {
            accB = add2(accB, b2B);
            float c2B0, c2B1; unpack2(accB, c2B0, c2B1);
            float m0 = __fsub_rn(__fmaf_rn(BETA, mem2B0, c2B0), spk2B0);
            float m1 = __fsub_rn(__fmaf_rn(BETA, mem2B1, c2B1), spk2B1);
            mem2B0 = m0; mem2B1 = m1;
            spk2B0 = (m0 > 1.0f) ? 1.0f : 0.0f;
            spk2B1 = (m1 > 1.0f) ? 1.0f : 0.0f;
            float2 sv; sv.x = spk2B0; sv.y = spk2B1;
            *(float2*)(spkout + offB) = sv;
            float2 mv; mv.x = m0; mv.y = m1;
            *(float2*)(memout + offB) = mv;
        }

        spkout += step_stride;
        memout += step_stride;
    }
}

extern "C" void kernel_launch(void* const* d_in, const int* in_sizes, int n_in,
                              void* d_out, int out_size) {
    const float* x  = (const float*)d_in[0];
    const float* W1 = (const float*)d_in[1];
    const float* b1 = (const float*)d_in[2];
    const float* W2 = (const float*)d_in[3];
    const float* b2 = (const float*)d_in[4];
    float* out = (float*)d_out;
    const int B = in_sizes[0] / NIN;
    const int grid = (B + SPB - 1) / SPB;
    snn_kernel<<<grid, 256>>>(x, W1, b1, W2, b2, out, B);
}

// round 5
// speedup vs baseline: 1.6364x; 1.6364x over previous
#include <cuda_runtime.h>
#include <cstdint>

// SNN: fc1(21->100) -> 25-step Leaky -> fc2(100->10) -> Leaky
// Numerics bitwise-identical to R4 (passing) kernel:
//  - cur1: acc=0, FMA k ascending, + b1 at end
//  - cur2: ordered sum of W2 columns over active j ascending (+0.0 pads are
//    exact identities), + b2 at end; add2 = per-lane scalar RN
//  - membrane: mem = fl(fma(beta,mem,cur)) then predicated fl(m - 1.0)
// Layout: 2 threads/sample, 50 neurons each; masks exchanged via 2 shfl;
// pairs {0,1,4} on tsub0, {2,3,dummy} on tsub1 -> uniform LDS.128+LDS.64
// + 3 add2 per active bit; walk unrolled x2 with zero-row padding.

#define BETA    0.99f
#define NSTEPS  25
#define H1      100
#define H2      10
#define NIN     21
#define JPT     50
#define TPB     256
#define SPB     (TPB/2)

typedef unsigned long long u64;
typedef unsigned int u32;

__device__ __forceinline__ u64 add2(u64 a, u64 b) {
    u64 d;
    asm("add.rn.f32x2 %0, %1, %2;" : "=l"(d) : "l"(a), "l"(b));
    return d;
}
__device__ __forceinline__ void unpack2(u64 v, float& a, float& b) {
    asm("mov.b64 {%0, %1}, %2;" : "=f"(a), "=f"(b) : "l"(v));
}

__global__ __launch_bounds__(TPB, 2)
void snn_kernel(const float* __restrict__ x,
                const float* __restrict__ W1,
                const float* __restrict__ b1,
                const float* __restrict__ W2,
                const float* __restrict__ b2,
                float* __restrict__ out,
                int B)
{
    __shared__ __align__(16) float W1s[H1][24];    // [j][k]
    __shared__ __align__(16) float W2s[104][12];   // [j][k] transposed; rows 100..103 zero
    __shared__ __align__(16) float b1s[H1];
    __shared__ __align__(16) float b2s[12];

    const int tid = threadIdx.x;

    for (int idx = tid; idx < H1 * NIN; idx += TPB)
        W1s[idx / NIN][idx % NIN] = W1[idx];
    for (int idx = tid; idx < H2 * H1; idx += TPB)
        W2s[idx % H1][idx / H1] = W2[idx];          // W2 is [10][100]
    if (tid < 48) ((float*)&W2s[100][0])[tid] = 0.0f;   // zero pad rows
    if (tid < H1) b1s[tid] = b1[tid];
    if (tid < 12) b2s[tid] = (tid < H2) ? b2[tid] : 0.0f;
    __syncthreads();

    const int tsub   = tid & 1;
    const int sample = blockIdx.x * SPB + (tid >> 1);
    if (sample >= B) return;
    const int jbase = tsub * JPT;

    // ---- x row ----
    float xr[NIN];
    const float* xrow = x + (size_t)sample * NIN;
#pragma unroll
    for (int i = 0; i < NIN; i++) xr[i] = __ldg(xrow + i);

    // ---- cur1: acc=0, FMA k ascending, then + b1 (50 rows) ----
    float cur1[JPT];
#pragma unroll
    for (int jj = 0; jj < JPT; jj++) {
        const float* w = &W1s[jbase + jj][0];
        float acc = 0.0f;
#pragma unroll
        for (int k = 0; k < NIN; k++)
            acc = __fmaf_rn(xr[k], w[k], acc);
        cur1[jj] = __fadd_rn(acc, b1s[jbase + jj]);
    }

    float mem1[JPT];
#pragma unroll
    for (int jj = 0; jj < JPT; jj++) mem1[jj] = 0.0f;
    u32 mAo = 0, mBo = 0;   // own masks: neurons jbase+0..24, jbase+25..49

    // layer-2 state: 3 pairs per thread (tsub1's third is a dummy)
    float mem2[6], spk2[6];
#pragma unroll
    for (int k = 0; k < 6; k++) { mem2[k] = 0.0f; spk2[k] = 0.0f; }

    const int woff = tsub * 4;                 // float offset of the .128 load
    const u64 B0 = *(const u64*)&b2s[tsub * 4];
    const u64 B1 = *(const u64*)&b2s[tsub * 4 + 2];
    const u64 B2 = *(const u64*)&b2s[8];

    float* spkout = out + (size_t)sample * H2;
    float* memout = spkout + (size_t)NSTEPS * B * H2;
    const size_t step_stride = (size_t)B * H2;

#pragma unroll 1
    for (int t = 0; t < NSTEPS; t++) {
        // ---- layer-1: mem = fma(beta,mem,cur); if(spiked_prev) mem -= 1.0 ----
        u32 nA = 0, nB = 0;
#pragma unroll
        for (int k = 0; k < 25; k++) {
            float mv = __fmaf_rn(BETA, mem1[k], cur1[k]);
            if ((mAo >> k) & 1u) mv = __fsub_rn(mv, 1.0f);
            mem1[k] = mv;
            if (mv > 1.0f) nA |= (1u << k);
        }
#pragma unroll
        for (int k = 0; k < 25; k++) {
            float mv = __fmaf_rn(BETA, mem1[25 + k], cur1[25 + k]);
            if ((mBo >> k) & 1u) mv = __fsub_rn(mv, 1.0f);
            mem1[25 + k] = mv;
            if (mv > 1.0f) nB |= (1u << k);
        }
        mAo = nA; mBo = nB;

        // ---- exchange masks; arrange in global ascending-j order ----
        u32 pA = __shfl_xor_sync(0xffffffffu, mAo, 1, 32);
        u32 pB = __shfl_xor_sync(0xffffffffu, mBo, 1, 32);
        u32 M0 = tsub ? pA : mAo;
        u32 M1 = tsub ? pB : mBo;
        u32 M2 = tsub ? mAo : pA;
        u32 M3 = tsub ? mBo : pB;

        // ---- cur2: ordered column-sum; 3 chains/thread; unroll-2 + zero-row ----
        u64 acc0 = 0ull, acc1 = 0ull, acc2 = 0ull;

#define WALK(MM, RB)                                                          \
        {                                                                     \
            u32 m = (MM);                                                     \
            while (m) {                                                       \
                int b0 = __ffs(m) - 1; m &= m - 1;                            \
                int b1i = __ffs(m) - 1;                                       \
                b1i = (m == 0) ? (100 - (RB)) : b1i;                          \
                m &= m - 1;                                                   \
                const float* w0 = &W2s[(RB) + b0][0];                         \
                const float* w1 = &W2s[(RB) + b1i][0];                        \
                ulonglong2 q0 = *(const ulonglong2*)(w0 + woff);              \
                u64 r0 = *(const u64*)(w0 + 8);                               \
                ulonglong2 q1 = *(const ulonglong2*)(w1 + woff);              \
                u64 r1 = *(const u64*)(w1 + 8);                               \
                acc0 = add2(acc0, q0.x); acc1 = add2(acc1, q0.y);             \
                acc2 = add2(acc2, r0);                                        \
                acc0 = add2(acc0, q1.x); acc1 = add2(acc1, q1.y);             \
                acc2 = add2(acc2, r1);                                        \
            }                                                                 \
        }
        WALK(M0, 0)
        WALK(M1, 25)
        WALK(M2, 50)
        WALK(M3, 75)
#undef WALK

        acc0 = add2(acc0, B0);
        acc1 = add2(acc1, B1);
        acc2 = add2(acc2, B2);

        float c[6];
        unpack2(acc0, c[0], c[1]);
        unpack2(acc1, c[2], c[3]);
        unpack2(acc2, c[4], c[5]);

        // ---- layer-2: mem = fl(fma(beta,mem,cur) - spk_prev) ----
#pragma unroll
        for (int k = 0; k < 6; k++) {
            float mv = __fsub_rn(__fmaf_rn(BETA, mem2[k], c[k]), spk2[k]);
            mem2[k] = mv;
            spk2[k] = (mv > 1.0f) ? 1.0f : 0.0f;
        }

        // ---- stores: tsub0 pairs {0,1,4}, tsub1 pairs {2,3} ----
        {
            const int o0 = tsub * 4, o1 = tsub * 4 + 2;
            float2 s0; s0.x = spk2[0]; s0.y = spk2[1];
            float2 s1; s1.x = spk2[2]; s1.y = spk2[3];
            float2 m0; m0.x = mem2[0]; m0.y = mem2[1];
            float2 m1; m1.x = mem2[2]; m1.y = mem2[3];
            *(float2*)(spkout + o0) = s0;
            *(float2*)(spkout + o1) = s1;
            *(float2*)(memout + o0) = m0;
            *(float2*)(memout + o1) = m1;
            if (tsub == 0) {
                float2 s2; s2.x = spk2[4]; s2.y = spk2[5];
                float2 m2; m2.x = mem2[4]; m2.y = mem2[5];
                *(float2*)(spkout + 8) = s2;
                *(float2*)(memout + 8) = m2;
            }
        }

        spkout += step_stride;
        memout += step_stride;
    }
}

extern "C" void kernel_launch(void* const* d_in, const int* in_sizes, int n_in,
                              void* d_out, int out_size) {
    const float* x  = (const float*)d_in[0];
    const float* W1 = (const float*)d_in[1];
    const float* b1 = (const float*)d_in[2];
    const float* W2 = (const float*)d_in[3];
    const float* b2 = (const float*)d_in[4];
    float* out = (float*)d_out;
    const int B = in_sizes[0] / NIN;
    const int grid = (B + SPB - 1) / SPB;
    snn_kernel<<<grid, TPB>>>(x, W1, b1, W2, b2, out, B);
}